// round 11
// baseline (speedup 1.0000x reference)
#include <cuda_runtime.h>
#include <cuda_bf16.h>

#define N_NODES 100000
#define F_IN 256
#define F_OUT 16

#define NPB 512
#define KC 16
#define XSTR 514
#define PSMEM (KC * XSTR * 4 + F_IN * F_OUT * 8)   // 32896 + 32768 = 65664 B

typedef unsigned long long ull;

// Scratch (static __device__ — no allocation allowed). Zero-init at load;
// g_deg re-zeroed each run in the final phase (self-loop folded as deg+1).
__device__ __align__(16) float g_deg[N_NODES];
__device__ __align__(16) float g_hn1[N_NODES * F_OUT];
__device__ __align__(16) float g_agg1[N_NODES * F_OUT];
__device__ __align__(16) float g_hn2[N_NODES];
__device__ __align__(16) float g_agg2[N_NODES];
__device__ unsigned g_barctr = 0;
__device__ unsigned g_done   = 0;

#define FFMA2(d, a, b) asm("fma.rn.f32x2 %0, %1, %2, %0;" : "+l"(d) : "l"(a), "l"(b))
#define REDV4(p, v) asm volatile("red.global.add.v4.f32 [%0], {%1, %2, %3, %4};" \
    :: "l"(p), "f"((v).x), "f"((v).y), "f"((v).z), "f"((v).w) : "memory")

// Cumulative-count grid barrier: all blocks resident (grid = nsm*occ).
__device__ __forceinline__ void grid_bar(unsigned target) {
    __syncthreads();
    if (threadIdx.x == 0) {
        __threadfence();                       // release
        atomicAdd(&g_barctr, 1u);
        while (*(volatile unsigned*)&g_barctr < target) __nanosleep(64);
        __threadfence();                       // acquire
    }
    __syncthreads();
}

__global__ __launch_bounds__(256, 3) void k_persist(
    const float* __restrict__ x,  const float* __restrict__ W1,
    const float* __restrict__ b1, const float* __restrict__ W2,
    const float* __restrict__ b2, const int* __restrict__ src,
    const int* __restrict__ dst,  int E, float* __restrict__ out)
{
    extern __shared__ float smem[];
    float*  sX  = smem;                          // [KC][XSTR]
    float2* sWd = (float2*)(smem + KC * XSTR);   // [F_IN][F_OUT] duplicated pairs
    const int tid  = threadIdx.x;
    const int nblk = gridDim.x;

    // Preload W1 duplicated pairs (sync covered by first gemm-tile barrier,
    // and explicitly below for blocks that start with deg chunks).
    for (int i = tid; i < F_IN * F_OUT; i += 256) {
        float w = W1[i];
        sWd[i] = make_float2(w, w);
    }
    __syncthreads();

    // ================= Phase A: GEMM1 raw + degree atomics =================
    const int nGemm = (N_NODES + NPB - 1) / NPB;          // 196
    const int E4    = E >> 2;
    const int nDeg  = (E4 + 1 + 255) / 256;
    for (int u = blockIdx.x; u < nGemm + nDeg; u += nblk) {
        if (u < nGemm) {
            // ---- one 512-node GEMM tile (R7-proven layout) ----
            int n0 = u * NPB;
            int nq = tid >> 2;          // 0..63
            int fq = tid & 3;           // 0..3
            ull acc[4][4];
            #pragma unroll
            for (int f = 0; f < 4; f++)
                #pragma unroll
                for (int p = 0; p < 4; p++) acc[f][p] = 0ull;

            for (int kc = 0; kc < F_IN; kc += KC) {
                __syncthreads();
                #pragma unroll
                for (int j = 0; j < (NPB * KC / 4) / 256; j++) {   // 8 iters
                    int i = tid + j * 256;
                    int n = i >> 2;          // 0..511
                    int kq = i & 3;
                    int row = n0 + n; if (row >= N_NODES) row = N_NODES - 1;
                    float4 v = __ldg((const float4*)(x + (size_t)row * F_IN + kc) + kq);
                    sX[(kq * 4 + 0) * XSTR + n] = v.x;
                    sX[(kq * 4 + 1) * XSTR + n] = v.y;
                    sX[(kq * 4 + 2) * XSTR + n] = v.z;
                    sX[(kq * 4 + 3) * XSTR + n] = v.w;
                }
                __syncthreads();
                #pragma unroll 4
                for (int k = 0; k < KC; k++) {
                    const float* xp = sX + k * XSTR + nq * 8;
                    ull xa0 = *(const ull*)xp;
                    ull xa1 = *(const ull*)(xp + 2);
                    ull xa2 = *(const ull*)(xp + 4);
                    ull xa3 = *(const ull*)(xp + 6);
                    const ulonglong2* wp =
                        (const ulonglong2*)(sWd + (kc + k) * F_OUT + fq * 4);
                    ulonglong2 w01 = wp[0];
                    ulonglong2 w23 = wp[1];
                    FFMA2(acc[0][0], xa0, w01.x); FFMA2(acc[0][1], xa1, w01.x);
                    FFMA2(acc[0][2], xa2, w01.x); FFMA2(acc[0][3], xa3, w01.x);
                    FFMA2(acc[1][0], xa0, w01.y); FFMA2(acc[1][1], xa1, w01.y);
                    FFMA2(acc[1][2], xa2, w01.y); FFMA2(acc[1][3], xa3, w01.y);
                    FFMA2(acc[2][0], xa0, w23.x); FFMA2(acc[2][1], xa1, w23.x);
                    FFMA2(acc[2][2], xa2, w23.x); FFMA2(acc[2][3], xa3, w23.x);
                    FFMA2(acc[3][0], xa0, w23.y); FFMA2(acc[3][1], xa1, w23.y);
                    FFMA2(acc[3][2], xa2, w23.y); FFMA2(acc[3][3], xa3, w23.y);
                }
            }
            #pragma unroll
            for (int j = 0; j < 8; j++) {
                int node = n0 + nq * 8 + j;
                if (node >= N_NODES) break;
                int p = j >> 1, hi = j & 1;
                union { ull u; float2 f; } c0, c1, c2, c3;
                c0.u = acc[0][p]; c1.u = acc[1][p]; c2.u = acc[2][p]; c3.u = acc[3][p];
                float4 o;
                o.x = hi ? c0.f.y : c0.f.x;
                o.y = hi ? c1.f.y : c1.f.x;
                o.z = hi ? c2.f.y : c2.f.x;
                o.w = hi ? c3.f.y : c3.f.x;
                *((float4*)(g_hn1 + (size_t)node * F_OUT) + fq) = o;   // raw
            }
        } else {
            // ---- degree chunk ----
            int t = (u - nGemm) * 256 + tid;
            if (t <= E4) {
                if (((E & 3) == 0) && t < E4) {
                    int4 d = __ldg((const int4*)dst + t);
                    atomicAdd(&g_deg[d.x], 1.0f);
                    atomicAdd(&g_deg[d.y], 1.0f);
                    atomicAdd(&g_deg[d.z], 1.0f);
                    atomicAdd(&g_deg[d.w], 1.0f);
                } else {
                    int e_end = t * 4 + 4; if (e_end > E) e_end = E;
                    for (int e = t * 4; e < e_end; e++)
                        atomicAdd(&g_deg[dst[e]], 1.0f);
                }
            }
        }
    }
    grid_bar(1u * nblk);

    // ================= Phase B: scale hn1, init agg1 (self-loop) ==========
    const int nScale = (N_NODES * 4 + 255) / 256;
    for (int u = blockIdx.x; u < nScale; u += nblk) {
        int t = u * 256 + tid;
        int n = t >> 2, fq = t & 3;
        if (n < N_NODES) {
            float isq = rsqrtf(g_deg[n] + 1.0f);
            float4* hp = (float4*)(g_hn1 + (size_t)n * F_OUT) + fq;
            float4 o = *hp;
            o.x *= isq; o.y *= isq; o.z *= isq; o.w *= isq;
            *hp = o;
            *((float4*)(g_agg1 + (size_t)n * F_OUT) + fq) = o;
        }
    }
    grid_bar(2u * nblk);

    // ================= Phase C: edge1 agg1[dst] += hn1[src] ===============
    if ((E & 3) == 0) {
        int Eq = E >> 2;
        int nC = (E + 255) / 256;                  // threads = Eq*4 = E
        for (int u = blockIdx.x; u < nC; u += nblk) {
            int t = u * 256 + tid;
            int q = t >> 2, c = t & 3;
            if (q < Eq) {
                int e0 = q, e1 = q + Eq, e2 = q + 2 * Eq, e3 = q + 3 * Eq;
                int s0 = __ldg(src + e0), d0 = __ldg(dst + e0);
                int s1 = __ldg(src + e1), d1 = __ldg(dst + e1);
                int s2 = __ldg(src + e2), d2 = __ldg(dst + e2);
                int s3 = __ldg(src + e3), d3 = __ldg(dst + e3);
                float4 v0 = __ldg((const float4*)(g_hn1 + (size_t)s0 * F_OUT) + c);
                float4 v1 = __ldg((const float4*)(g_hn1 + (size_t)s1 * F_OUT) + c);
                float4 v2 = __ldg((const float4*)(g_hn1 + (size_t)s2 * F_OUT) + c);
                float4 v3 = __ldg((const float4*)(g_hn1 + (size_t)s3 * F_OUT) + c);
                REDV4(g_agg1 + (size_t)d0 * F_OUT + c * 4, v0);
                REDV4(g_agg1 + (size_t)d1 * F_OUT + c * 4, v1);
                REDV4(g_agg1 + (size_t)d2 * F_OUT + c * 4, v2);
                REDV4(g_agg1 + (size_t)d3 * F_OUT + c * 4, v3);
            }
        }
    } else {
        long long ET = (long long)E * 4;
        int nC = (int)((ET + 255) / 256);
        for (int u = blockIdx.x; u < nC; u += nblk) {
            long long t = (long long)u * 256 + tid;
            int e = (int)(t >> 2), c = (int)(t & 3);
            if (e < E) {
                int s = __ldg(src + e), d = __ldg(dst + e);
                float4 v = __ldg((const float4*)(g_hn1 + (size_t)s * F_OUT) + c);
                REDV4(g_agg1 + (size_t)d * F_OUT + c * 4, v);
            }
        }
    }
    grid_bar(3u * nblk);

    // ================= Phase D: node2 (relu+bias+16->1+scale) =============
    // agg1 was RED-modified in L2 only -> bypass L1 with __ldcv.
    const int nNode = (N_NODES + 255) / 256;
    for (int u = blockIdx.x; u < nNode; u += nblk) {
        int n = u * 256 + tid;
        if (n < N_NODES) {
            float isq = rsqrtf(g_deg[n] + 1.0f);
            const float4* ar = (const float4*)(g_agg1 + (size_t)n * F_OUT);
            float h2 = 0.0f;
            #pragma unroll
            for (int c = 0; c < 4; c++) {
                float4 a = __ldcv(ar + c);
                float v;
                v = fmaxf(fmaf(isq, a.x, __ldg(b1 + c * 4 + 0)), 0.0f); h2 = fmaf(v, __ldg(W2 + c * 4 + 0), h2);
                v = fmaxf(fmaf(isq, a.y, __ldg(b1 + c * 4 + 1)), 0.0f); h2 = fmaf(v, __ldg(W2 + c * 4 + 1), h2);
                v = fmaxf(fmaf(isq, a.z, __ldg(b1 + c * 4 + 2)), 0.0f); h2 = fmaf(v, __ldg(W2 + c * 4 + 2), h2);
                v = fmaxf(fmaf(isq, a.w, __ldg(b1 + c * 4 + 3)), 0.0f); h2 = fmaf(v, __ldg(W2 + c * 4 + 3), h2);
            }
            float v2 = h2 * isq;
            g_hn2[n]  = v2;
            g_agg2[n] = v2;              // self-loop init
        }
    }
    grid_bar(4u * nblk);

    // ================= Phase E: edge2 agg2[dst] += hn2[src] ===============
    {
        int E8 = E >> 3;
        int nE2 = (E8 + 1 + 255) / 256;
        for (int u = blockIdx.x; u < nE2; u += nblk) {
            int t = u * 256 + tid;
            if (t < E8) {
                int4 sa = __ldg((const int4*)src + 2 * t);
                int4 sb = __ldg((const int4*)src + 2 * t + 1);
                int4 da = __ldg((const int4*)dst + 2 * t);
                int4 db = __ldg((const int4*)dst + 2 * t + 1);
                float ha = __ldg(g_hn2 + sa.x), hb = __ldg(g_hn2 + sa.y);
                float hc = __ldg(g_hn2 + sa.z), hd = __ldg(g_hn2 + sa.w);
                float he = __ldg(g_hn2 + sb.x), hf = __ldg(g_hn2 + sb.y);
                float hg = __ldg(g_hn2 + sb.z), hh = __ldg(g_hn2 + sb.w);
                atomicAdd(&g_agg2[da.x], ha);
                atomicAdd(&g_agg2[da.y], hb);
                atomicAdd(&g_agg2[da.z], hc);
                atomicAdd(&g_agg2[da.w], hd);
                atomicAdd(&g_agg2[db.x], he);
                atomicAdd(&g_agg2[db.y], hf);
                atomicAdd(&g_agg2[db.z], hg);
                atomicAdd(&g_agg2[db.w], hh);
            } else if (t == E8) {
                for (int e = E8 * 8; e < E; e++)
                    atomicAdd(&g_agg2[dst[e]], g_hn2[src[e]]);
            }
        }
    }
    grid_bar(5u * nblk);

    // ================= Phase F: final output + state reset ================
    for (int u = blockIdx.x; u < nNode; u += nblk) {
        int n = u * 256 + tid;
        if (n < N_NODES) {
            float d = g_deg[n];
            out[n] = fmaf(rsqrtf(d + 1.0f), __ldcv(&g_agg2[n]), __ldg(b2));
            g_deg[n] = 0.0f;              // ready for next replay
        }
    }
    // reset barrier counters (last block to finish does it)
    __syncthreads();
    if (tid == 0) {
        __threadfence();
        unsigned d = atomicAdd(&g_done, 1u);
        if (d == (unsigned)nblk - 1u) {
            atomicExch(&g_barctr, 0u);
            atomicExch(&g_done, 0u);
        }
    }
}

// ---------------------------------------------------------------------------
extern "C" void kernel_launch(void* const* d_in, const int* in_sizes, int n_in,
                              void* d_out, int out_size) {
    const float* x  = (const float*)d_in[0];
    const int*   ei = (const int*)d_in[1];
    const float* W1 = (const float*)d_in[2];
    const float* b1 = (const float*)d_in[3];
    const float* W2 = (const float*)d_in[4];
    const float* b2 = (const float*)d_in[5];
    float* out = (float*)d_out;

    int E = in_sizes[1] / 2;
    const int* src = ei;
    const int* dst = ei + E;

    cudaFuncSetAttribute(k_persist, cudaFuncAttributeMaxDynamicSharedMemorySize,
                         PSMEM);

    int dev = 0;
    cudaGetDevice(&dev);
    int nsm = 0;
    cudaDeviceGetAttribute(&nsm, cudaDevAttrMultiProcessorCount, dev);
    if (nsm <= 0) nsm = 148;
    int occ = 0;
    cudaOccupancyMaxActiveBlocksPerMultiprocessor(&occ, k_persist, 256, PSMEM);
    if (occ <= 0) occ = 1;
    int nblk = nsm * occ;

    k_persist<<<nblk, 256, PSMEM>>>(x, W1, b1, W2, b2, src, dst, E, out);
}

// round 12
// speedup vs baseline: 1.0771x; 1.0771x over previous
#include <cuda_runtime.h>
#include <cuda_bf16.h>

#define N_NODES 100000
#define F_IN 256
#define F_OUT 16

// --- GEMM kernel config (R7-proven) ---
#define NPB 512
#define KC 32
#define XSTR 514
#define GEMM_SMEM (KC * XSTR * 4 + F_IN * F_OUT * 8)

typedef unsigned long long ull;

// Scratch (static __device__ — no allocation allowed). Zero-init at load;
// g_deg re-zeroed each run in the final phase (self-loop folded as deg+1).
__device__ __align__(16) float g_deg[N_NODES];
__device__ __align__(16) float g_hn1[N_NODES * F_OUT];
__device__ __align__(16) float g_agg1[N_NODES * F_OUT];
__device__ __align__(16) float g_hn2[N_NODES];
__device__ __align__(16) float g_agg2[N_NODES];
__device__ unsigned g_barctr = 0;
__device__ unsigned g_done   = 0;

#define FFMA2(d, a, b) asm("fma.rn.f32x2 %0, %1, %2, %0;" : "+l"(d) : "l"(a), "l"(b))
#define REDV4(p, v) asm volatile("red.global.add.v4.f32 [%0], {%1, %2, %3, %4};" \
    :: "l"(p), "f"((v).x), "f"((v).y), "f"((v).z), "f"((v).w) : "memory")

// ---------------------------------------------------------------------------
// K1 (fused): blocks [0, nbGemm) = GEMM1 raw (hn1 = x@W1, unscaled);
//             blocks [nbGemm, ..) = degree atomics (independent of GEMM).
__global__ __launch_bounds__(256, 2) void k_fused(const float* __restrict__ x,
                                                  const float* __restrict__ W1,
                                                  const int* __restrict__ dst,
                                                  int E, int nbGemm) {
    extern __shared__ float smem[];
    int tid = threadIdx.x;

    if (blockIdx.x >= nbGemm) {
        int E4 = E >> 2;
        int t = (blockIdx.x - nbGemm) * 256 + tid;
        if (t < E4) {
            int4 d = __ldg((const int4*)dst + t);
            atomicAdd(&g_deg[d.x], 1.0f);
            atomicAdd(&g_deg[d.y], 1.0f);
            atomicAdd(&g_deg[d.z], 1.0f);
            atomicAdd(&g_deg[d.w], 1.0f);
        } else if (t == E4) {
            for (int e = E4 * 4; e < E; e++) atomicAdd(&g_deg[dst[e]], 1.0f);
        }
        return;
    }

    float*  sX  = smem;                          // [KC][XSTR]
    float2* sWd = (float2*)(smem + KC * XSTR);   // [F_IN][F_OUT] duplicated pairs

    int n0 = blockIdx.x * NPB;
    for (int i = tid; i < F_IN * F_OUT; i += 256) {
        float w = W1[i];
        sWd[i] = make_float2(w, w);
    }

    int nq = tid >> 2;      // 0..63 -> nodes nq*8 .. nq*8+7
    int fq = tid & 3;       // 0..3

    ull acc[4][4];
    #pragma unroll
    for (int f = 0; f < 4; f++)
        #pragma unroll
        for (int p = 0; p < 4; p++) acc[f][p] = 0ull;

    for (int kc = 0; kc < F_IN; kc += KC) {
        __syncthreads();
        #pragma unroll
        for (int j = 0; j < (NPB * KC / 4) / 256; j++) {   // 16 iters
            int i = tid + j * 256;
            int n = i >> 3;
            int kq = i & 7;
            int row = n0 + n; if (row >= N_NODES) row = N_NODES - 1;
            float4 v = __ldg((const float4*)(x + (size_t)row * F_IN + kc) + kq);
            sX[(kq * 4 + 0) * XSTR + n] = v.x;
            sX[(kq * 4 + 1) * XSTR + n] = v.y;
            sX[(kq * 4 + 2) * XSTR + n] = v.z;
            sX[(kq * 4 + 3) * XSTR + n] = v.w;
        }
        __syncthreads();
        #pragma unroll 4
        for (int k = 0; k < KC; k++) {
            const float* xp = sX + k * XSTR + nq * 8;
            ull xa0 = *(const ull*)xp;
            ull xa1 = *(const ull*)(xp + 2);
            ull xa2 = *(const ull*)(xp + 4);
            ull xa3 = *(const ull*)(xp + 6);
            const ulonglong2* wp = (const ulonglong2*)(sWd + (kc + k) * F_OUT + fq * 4);
            ulonglong2 w01 = wp[0];
            ulonglong2 w23 = wp[1];
            FFMA2(acc[0][0], xa0, w01.x); FFMA2(acc[0][1], xa1, w01.x);
            FFMA2(acc[0][2], xa2, w01.x); FFMA2(acc[0][3], xa3, w01.x);
            FFMA2(acc[1][0], xa0, w01.y); FFMA2(acc[1][1], xa1, w01.y);
            FFMA2(acc[1][2], xa2, w01.y); FFMA2(acc[1][3], xa3, w01.y);
            FFMA2(acc[2][0], xa0, w23.x); FFMA2(acc[2][1], xa1, w23.x);
            FFMA2(acc[2][2], xa2, w23.x); FFMA2(acc[2][3], xa3, w23.x);
            FFMA2(acc[3][0], xa0, w23.y); FFMA2(acc[3][1], xa1, w23.y);
            FFMA2(acc[3][2], xa2, w23.y); FFMA2(acc[3][3], xa3, w23.y);
        }
    }

    #pragma unroll
    for (int j = 0; j < 8; j++) {
        int node = n0 + nq * 8 + j;
        if (node >= N_NODES) break;
        int p = j >> 1, hi = j & 1;
        union { ull u; float2 f; } c0, c1, c2, c3;
        c0.u = acc[0][p]; c1.u = acc[1][p]; c2.u = acc[2][p]; c3.u = acc[3][p];
        float4 o;
        o.x = hi ? c0.f.y : c0.f.x;
        o.y = hi ? c1.f.y : c1.f.x;
        o.z = hi ? c2.f.y : c2.f.x;
        o.w = hi ? c3.f.y : c3.f.x;
        *((float4*)(g_hn1 + (size_t)node * F_OUT) + fq) = o;   // raw, unscaled
    }
}

// ---------------------------------------------------------------------------
// K2 (persistent, NO smem, high occupancy): scale -> edge1 -> node2 -> edge2
// -> final, separated by grid barriers (all blocks resident: grid = nsm*occ).
__device__ __forceinline__ void grid_bar(unsigned target) {
    __syncthreads();
    if (threadIdx.x == 0) {
        __threadfence();                       // release
        atomicAdd(&g_barctr, 1u);
        while (*(volatile unsigned*)&g_barctr < target) __nanosleep(64);
        __threadfence();                       // acquire
    }
    __syncthreads();
}

__global__ __launch_bounds__(256, 6) void k_rest(
    const float* __restrict__ b1, const float* __restrict__ W2,
    const float* __restrict__ b2, const int* __restrict__ src,
    const int* __restrict__ dst,  int E, float* __restrict__ out)
{
    const int tid  = threadIdx.x;
    const int nblk = gridDim.x;

    // ===== Phase B: scale hn1 by isq, init agg1 (self-loop) =====
    // Each hn1/agg1 row is read+written by exactly one thread -> L1-safe.
    const int nScale = (N_NODES * 4 + 255) / 256;
    for (int u = blockIdx.x; u < nScale; u += nblk) {
        int t = u * 256 + tid;
        int n = t >> 2, fq = t & 3;
        if (n < N_NODES) {
            float isq = rsqrtf(g_deg[n] + 1.0f);
            float4* hp = (float4*)(g_hn1 + (size_t)n * F_OUT) + fq;
            float4 o = *hp;
            o.x *= isq; o.y *= isq; o.z *= isq; o.w *= isq;
            *hp = o;
            *((float4*)(g_agg1 + (size_t)n * F_OUT) + fq) = o;
        }
    }
    grid_bar(1u * nblk);

    // ===== Phase C: edge1 agg1[dst] += hn1[src] (4 lanes/edge, 4 chains) ===
    if ((E & 3) == 0) {
        int Eq = E >> 2;
        int nC = (E + 255) / 256;
        for (int u = blockIdx.x; u < nC; u += nblk) {
            int t = u * 256 + tid;
            int q = t >> 2, c = t & 3;
            if (q < Eq) {
                int e0 = q, e1 = q + Eq, e2 = q + 2 * Eq, e3 = q + 3 * Eq;
                int s0 = __ldg(src + e0), d0 = __ldg(dst + e0);
                int s1 = __ldg(src + e1), d1 = __ldg(dst + e1);
                int s2 = __ldg(src + e2), d2 = __ldg(dst + e2);
                int s3 = __ldg(src + e3), d3 = __ldg(dst + e3);
                float4 v0 = __ldg((const float4*)(g_hn1 + (size_t)s0 * F_OUT) + c);
                float4 v1 = __ldg((const float4*)(g_hn1 + (size_t)s1 * F_OUT) + c);
                float4 v2 = __ldg((const float4*)(g_hn1 + (size_t)s2 * F_OUT) + c);
                float4 v3 = __ldg((const float4*)(g_hn1 + (size_t)s3 * F_OUT) + c);
                REDV4(g_agg1 + (size_t)d0 * F_OUT + c * 4, v0);
                REDV4(g_agg1 + (size_t)d1 * F_OUT + c * 4, v1);
                REDV4(g_agg1 + (size_t)d2 * F_OUT + c * 4, v2);
                REDV4(g_agg1 + (size_t)d3 * F_OUT + c * 4, v3);
            }
        }
    } else {
        long long ET = (long long)E * 4;
        int nC = (int)((ET + 255) / 256);
        for (int u = blockIdx.x; u < nC; u += nblk) {
            long long t = (long long)u * 256 + tid;
            int e = (int)(t >> 2), c = (int)(t & 3);
            if (e < E) {
                int s = __ldg(src + e), d = __ldg(dst + e);
                float4 v = __ldg((const float4*)(g_hn1 + (size_t)s * F_OUT) + c);
                REDV4(g_agg1 + (size_t)d * F_OUT + c * 4, v);
            }
        }
    }
    grid_bar(2u * nblk);

    // ===== Phase D: node2 (relu+bias+16->1+scale); agg1 via __ldcv ========
    const int nNode = (N_NODES + 255) / 256;
    for (int u = blockIdx.x; u < nNode; u += nblk) {
        int n = u * 256 + tid;
        if (n < N_NODES) {
            float isq = rsqrtf(g_deg[n] + 1.0f);
            const float4* ar = (const float4*)(g_agg1 + (size_t)n * F_OUT);
            float h2 = 0.0f;
            #pragma unroll
            for (int c = 0; c < 4; c++) {
                float4 a = __ldcv(ar + c);
                float v;
                v = fmaxf(fmaf(isq, a.x, __ldg(b1 + c * 4 + 0)), 0.0f); h2 = fmaf(v, __ldg(W2 + c * 4 + 0), h2);
                v = fmaxf(fmaf(isq, a.y, __ldg(b1 + c * 4 + 1)), 0.0f); h2 = fmaf(v, __ldg(W2 + c * 4 + 1), h2);
                v = fmaxf(fmaf(isq, a.z, __ldg(b1 + c * 4 + 2)), 0.0f); h2 = fmaf(v, __ldg(W2 + c * 4 + 2), h2);
                v = fmaxf(fmaf(isq, a.w, __ldg(b1 + c * 4 + 3)), 0.0f); h2 = fmaf(v, __ldg(W2 + c * 4 + 3), h2);
            }
            float v2 = h2 * isq;
            g_hn2[n]  = v2;
            g_agg2[n] = v2;              // self-loop init
        }
    }
    grid_bar(3u * nblk);

    // ===== Phase E: edge2 agg2[dst] += hn2[src] (8 edges/thread) ==========
    {
        int E8 = E >> 3;
        int nE2 = (E8 + 1 + 255) / 256;
        for (int u = blockIdx.x; u < nE2; u += nblk) {
            int t = u * 256 + tid;
            if (t < E8) {
                int4 sa = __ldg((const int4*)src + 2 * t);
                int4 sb = __ldg((const int4*)src + 2 * t + 1);
                int4 da = __ldg((const int4*)dst + 2 * t);
                int4 db = __ldg((const int4*)dst + 2 * t + 1);
                float ha = __ldg(g_hn2 + sa.x), hb = __ldg(g_hn2 + sa.y);
                float hc = __ldg(g_hn2 + sa.z), hd = __ldg(g_hn2 + sa.w);
                float he = __ldg(g_hn2 + sb.x), hf = __ldg(g_hn2 + sb.y);
                float hg = __ldg(g_hn2 + sb.z), hh = __ldg(g_hn2 + sb.w);
                atomicAdd(&g_agg2[da.x], ha);
                atomicAdd(&g_agg2[da.y], hb);
                atomicAdd(&g_agg2[da.z], hc);
                atomicAdd(&g_agg2[da.w], hd);
                atomicAdd(&g_agg2[db.x], he);
                atomicAdd(&g_agg2[db.y], hf);
                atomicAdd(&g_agg2[db.z], hg);
                atomicAdd(&g_agg2[db.w], hh);
            } else if (t == E8) {
                for (int e = E8 * 8; e < E; e++)
                    atomicAdd(&g_agg2[dst[e]], g_hn2[src[e]]);
            }
        }
    }
    grid_bar(4u * nblk);

    // ===== Phase F: final output + state reset ============================
    for (int u = blockIdx.x; u < nNode; u += nblk) {
        int n = u * 256 + tid;
        if (n < N_NODES) {
            float d = g_deg[n];
            out[n] = fmaf(rsqrtf(d + 1.0f), __ldcv(&g_agg2[n]), __ldg(b2));
            g_deg[n] = 0.0f;              // ready for next replay
        }
    }
    __syncthreads();
    if (tid == 0) {
        __threadfence();
        unsigned d = atomicAdd(&g_done, 1u);
        if (d == (unsigned)nblk - 1u) {
            atomicExch(&g_barctr, 0u);
            atomicExch(&g_done, 0u);
        }
    }
}

// ---------------------------------------------------------------------------
extern "C" void kernel_launch(void* const* d_in, const int* in_sizes, int n_in,
                              void* d_out, int out_size) {
    const float* x  = (const float*)d_in[0];
    const int*   ei = (const int*)d_in[1];
    const float* W1 = (const float*)d_in[2];
    const float* b1 = (const float*)d_in[3];
    const float* W2 = (const float*)d_in[4];
    const float* b2 = (const float*)d_in[5];
    float* out = (float*)d_out;

    int E = in_sizes[1] / 2;
    const int* src = ei;
    const int* dst = ei + E;

    int nb_gemm = (N_NODES + NPB - 1) / NPB;
    int nb_deg  = ((E >> 2) + 1 + 255) / 256;

    cudaFuncSetAttribute(k_fused, cudaFuncAttributeMaxDynamicSharedMemorySize,
                         GEMM_SMEM);

    int dev = 0;
    cudaGetDevice(&dev);
    int nsm = 0;
    cudaDeviceGetAttribute(&nsm, cudaDevAttrMultiProcessorCount, dev);
    if (nsm <= 0) nsm = 148;
    int occ = 0;
    cudaOccupancyMaxActiveBlocksPerMultiprocessor(&occ, k_rest, 256, 0);
    if (occ <= 0) occ = 1;
    int nblk = nsm * occ;

    k_fused<<<nb_gemm + nb_deg, 256, GEMM_SMEM>>>(x, W1, dst, E, nb_gemm);
    k_rest<<<nblk, 256>>>(b1, W2, b2, src, dst, E, out);
}

// round 13
// speedup vs baseline: 1.2637x; 1.1733x over previous
#include <cuda_runtime.h>
#include <cuda_bf16.h>

#define N_NODES 100000
#define F_IN 256
#define F_OUT 16

#define NPB 512
#define KC 32
#define XSTR 514
#define GEMM_SMEM (KC * XSTR * 4 + F_IN * F_OUT * 8)

typedef unsigned long long ull;

// Scratch (static __device__ — no allocation allowed). Zero-init at load;
// g_deg re-zeroed each run in k_final (self-loop folded as deg+1).
__device__ __align__(16) float g_deg[N_NODES];
__device__ __align__(16) float g_hn1[N_NODES * F_OUT];
__device__ __align__(16) float g_agg1[N_NODES * F_OUT];
__device__ __align__(16) float g_hn2[N_NODES];
__device__ __align__(16) float g_agg2[N_NODES];

#define FFMA2(d, a, b) asm("fma.rn.f32x2 %0, %1, %2, %0;" : "+l"(d) : "l"(a), "l"(b))
#define REDV4(p, v) asm volatile("red.global.add.v4.f32 [%0], {%1, %2, %3, %4};" \
    :: "l"(p), "f"((v).x), "f"((v).y), "f"((v).z), "f"((v).w) : "memory")
#define PDL_WAIT()    asm volatile("griddepcontrol.wait;" ::: "memory")
#define PDL_TRIGGER() asm volatile("griddepcontrol.launch_dependents;" ::: "memory")

// ---------------------------------------------------------------------------
// K1 (fused): blocks [0, nbGemm) = GEMM1 raw (hn1 = x@W1, unscaled);
//             blocks [nbGemm, ..) = degree atomics.
// GEMM blocks read only inputs -> no wait. Deg blocks touch g_deg (reset by
// previous replay's k_final) -> PDL wait first.
__global__ __launch_bounds__(256, 2) void k_fused(const float* __restrict__ x,
                                                  const float* __restrict__ W1,
                                                  const int* __restrict__ dst,
                                                  int E, int nbGemm) {
    extern __shared__ float smem[];
    int tid = threadIdx.x;

    if (blockIdx.x >= nbGemm) {
        int E4 = E >> 2;
        int t = (blockIdx.x - nbGemm) * 256 + tid;
        // prefetch indices (input buffer, no dependency)
        int4 d = make_int4(0, 0, 0, 0);
        bool full = (t < E4);
        if (full) d = __ldg((const int4*)dst + t);
        PDL_WAIT();
        if (full) {
            atomicAdd(&g_deg[d.x], 1.0f);
            atomicAdd(&g_deg[d.y], 1.0f);
            atomicAdd(&g_deg[d.z], 1.0f);
            atomicAdd(&g_deg[d.w], 1.0f);
        } else if (t == E4) {
            for (int e = E4 * 4; e < E; e++) atomicAdd(&g_deg[dst[e]], 1.0f);
        }
        PDL_TRIGGER();
        return;
    }

    float*  sX  = smem;                          // [KC][XSTR]
    float2* sWd = (float2*)(smem + KC * XSTR);   // [F_IN][F_OUT] duplicated pairs

    int n0 = blockIdx.x * NPB;
    for (int i = tid; i < F_IN * F_OUT; i += 256) {
        float w = W1[i];
        sWd[i] = make_float2(w, w);
    }

    int nq = tid >> 2;      // 0..63 -> nodes nq*8 .. nq*8+7
    int fq = tid & 3;       // 0..3

    ull acc[4][4];
    #pragma unroll
    for (int f = 0; f < 4; f++)
        #pragma unroll
        for (int p = 0; p < 4; p++) acc[f][p] = 0ull;

    for (int kc = 0; kc < F_IN; kc += KC) {
        __syncthreads();
        #pragma unroll
        for (int j = 0; j < (NPB * KC / 4) / 256; j++) {   // 16 iters
            int i = tid + j * 256;
            int n = i >> 3;
            int kq = i & 7;
            int row = n0 + n; if (row >= N_NODES) row = N_NODES - 1;
            float4 v = __ldg((const float4*)(x + (size_t)row * F_IN + kc) + kq);
            sX[(kq * 4 + 0) * XSTR + n] = v.x;
            sX[(kq * 4 + 1) * XSTR + n] = v.y;
            sX[(kq * 4 + 2) * XSTR + n] = v.z;
            sX[(kq * 4 + 3) * XSTR + n] = v.w;
        }
        __syncthreads();
        #pragma unroll 4
        for (int k = 0; k < KC; k++) {
            const float* xp = sX + k * XSTR + nq * 8;
            ull xa0 = *(const ull*)xp;
            ull xa1 = *(const ull*)(xp + 2);
            ull xa2 = *(const ull*)(xp + 4);
            ull xa3 = *(const ull*)(xp + 6);
            const ulonglong2* wp = (const ulonglong2*)(sWd + (kc + k) * F_OUT + fq * 4);
            ulonglong2 w01 = wp[0];
            ulonglong2 w23 = wp[1];
            FFMA2(acc[0][0], xa0, w01.x); FFMA2(acc[0][1], xa1, w01.x);
            FFMA2(acc[0][2], xa2, w01.x); FFMA2(acc[0][3], xa3, w01.x);
            FFMA2(acc[1][0], xa0, w01.y); FFMA2(acc[1][1], xa1, w01.y);
            FFMA2(acc[1][2], xa2, w01.y); FFMA2(acc[1][3], xa3, w01.y);
            FFMA2(acc[2][0], xa0, w23.x); FFMA2(acc[2][1], xa1, w23.x);
            FFMA2(acc[2][2], xa2, w23.x); FFMA2(acc[2][3], xa3, w23.x);
            FFMA2(acc[3][0], xa0, w23.y); FFMA2(acc[3][1], xa1, w23.y);
            FFMA2(acc[3][2], xa2, w23.y); FFMA2(acc[3][3], xa3, w23.y);
        }
    }

    #pragma unroll
    for (int j = 0; j < 8; j++) {
        int node = n0 + nq * 8 + j;
        if (node >= N_NODES) break;
        int p = j >> 1, hi = j & 1;
        union { ull u; float2 f; } c0, c1, c2, c3;
        c0.u = acc[0][p]; c1.u = acc[1][p]; c2.u = acc[2][p]; c3.u = acc[3][p];
        float4 o;
        o.x = hi ? c0.f.y : c0.f.x;
        o.y = hi ? c1.f.y : c1.f.x;
        o.z = hi ? c2.f.y : c2.f.x;
        o.w = hi ? c3.f.y : c3.f.x;
        *((float4*)(g_hn1 + (size_t)node * F_OUT) + fq) = o;   // raw, unscaled
    }
    PDL_TRIGGER();
}

// ---------------------------------------------------------------------------
// K2: scale hn1 by isq, init agg1 (self-loop)
__global__ void k_scale() {
    int t = blockIdx.x * blockDim.x + threadIdx.x;
    int n = t >> 2;
    int fq = t & 3;
    PDL_WAIT();
    if (n < N_NODES) {
        float isq = rsqrtf(g_deg[n] + 1.0f);
        float4* hp = (float4*)(g_hn1 + (size_t)n * F_OUT) + fq;
        float4 o = *hp;
        o.x *= isq; o.y *= isq; o.z *= isq; o.w *= isq;
        *hp = o;
        *((float4*)(g_agg1 + (size_t)n * F_OUT) + fq) = o;
    }
    PDL_TRIGGER();
}

// ---------------------------------------------------------------------------
// K3: edge1 agg1[dst] += hn1[src]; 4 lanes/edge, 4 chains/thread.
// Indices prefetched BEFORE the PDL wait (input buffer, no dependency).
__global__ void k_edge1_v4(const int* __restrict__ src, const int* __restrict__ dst,
                           int Eq) {
    int t = blockIdx.x * blockDim.x + threadIdx.x;
    int q = t >> 2;
    int c = t & 3;
    bool act = (q < Eq);
    int s0 = 0, d0 = 0, s1 = 0, d1 = 0, s2 = 0, d2 = 0, s3 = 0, d3 = 0;
    if (act) {
        int e0 = q, e1 = q + Eq, e2 = q + 2 * Eq, e3 = q + 3 * Eq;
        s0 = __ldg(src + e0); d0 = __ldg(dst + e0);
        s1 = __ldg(src + e1); d1 = __ldg(dst + e1);
        s2 = __ldg(src + e2); d2 = __ldg(dst + e2);
        s3 = __ldg(src + e3); d3 = __ldg(dst + e3);
    }
    PDL_WAIT();
    if (act) {
        float4 v0 = __ldg((const float4*)(g_hn1 + (size_t)s0 * F_OUT) + c);
        float4 v1 = __ldg((const float4*)(g_hn1 + (size_t)s1 * F_OUT) + c);
        float4 v2 = __ldg((const float4*)(g_hn1 + (size_t)s2 * F_OUT) + c);
        float4 v3 = __ldg((const float4*)(g_hn1 + (size_t)s3 * F_OUT) + c);
        REDV4(g_agg1 + (size_t)d0 * F_OUT + c * 4, v0);
        REDV4(g_agg1 + (size_t)d1 * F_OUT + c * 4, v1);
        REDV4(g_agg1 + (size_t)d2 * F_OUT + c * 4, v2);
        REDV4(g_agg1 + (size_t)d3 * F_OUT + c * 4, v3);
    }
    PDL_TRIGGER();
}
__global__ void k_edge1_s(const int* __restrict__ src, const int* __restrict__ dst,
                          int E) {
    int t = blockIdx.x * blockDim.x + threadIdx.x;
    int e = t >> 2;
    int c = t & 3;
    bool act = (e < E);
    int s = 0, d = 0;
    if (act) { s = __ldg(src + e); d = __ldg(dst + e); }
    PDL_WAIT();
    if (act) {
        float4 v = __ldg((const float4*)(g_hn1 + (size_t)s * F_OUT) + c);
        REDV4(g_agg1 + (size_t)d * F_OUT + c * 4, v);
    }
    PDL_TRIGGER();
}

// ---------------------------------------------------------------------------
// K4: node2: relu+bias+16->1+scale. agg1 was RED-modified (L2) -> __ldcv.
__global__ void k_node2(const float* __restrict__ b1, const float* __restrict__ W2) {
    int n = blockIdx.x * blockDim.x + threadIdx.x;
    float bb[16], ww[16];
    #pragma unroll
    for (int i = 0; i < 16; i++) { bb[i] = __ldg(b1 + i); ww[i] = __ldg(W2 + i); }
    PDL_WAIT();
    if (n < N_NODES) {
        float isq = rsqrtf(g_deg[n] + 1.0f);
        const float4* ar = (const float4*)(g_agg1 + (size_t)n * F_OUT);
        float h2 = 0.0f;
        #pragma unroll
        for (int c = 0; c < 4; c++) {
            float4 a = __ldcv(ar + c);
            float v;
            v = fmaxf(fmaf(isq, a.x, bb[c * 4 + 0]), 0.0f); h2 = fmaf(v, ww[c * 4 + 0], h2);
            v = fmaxf(fmaf(isq, a.y, bb[c * 4 + 1]), 0.0f); h2 = fmaf(v, ww[c * 4 + 1], h2);
            v = fmaxf(fmaf(isq, a.z, bb[c * 4 + 2]), 0.0f); h2 = fmaf(v, ww[c * 4 + 2], h2);
            v = fmaxf(fmaf(isq, a.w, bb[c * 4 + 3]), 0.0f); h2 = fmaf(v, ww[c * 4 + 3], h2);
        }
        float v2 = h2 * isq;
        g_hn2[n]  = v2;
        g_agg2[n] = v2;              // self-loop init
    }
    PDL_TRIGGER();
}

// ---------------------------------------------------------------------------
// K5: edge2 agg2[dst] += hn2[src]; 8 edges/thread, indices prefetched pre-wait.
__global__ void k_edge2(const int* __restrict__ src, const int* __restrict__ dst,
                        int E) {
    int E8 = E >> 3;
    int t = blockIdx.x * blockDim.x + threadIdx.x;
    int4 sa, sb, da, db;
    bool full = (t < E8);
    if (full) {
        sa = __ldg((const int4*)src + 2 * t);
        sb = __ldg((const int4*)src + 2 * t + 1);
        da = __ldg((const int4*)dst + 2 * t);
        db = __ldg((const int4*)dst + 2 * t + 1);
    }
    PDL_WAIT();
    if (full) {
        float ha = __ldg(g_hn2 + sa.x), hb = __ldg(g_hn2 + sa.y);
        float hc = __ldg(g_hn2 + sa.z), hd = __ldg(g_hn2 + sa.w);
        float he = __ldg(g_hn2 + sb.x), hf = __ldg(g_hn2 + sb.y);
        float hg = __ldg(g_hn2 + sb.z), hh = __ldg(g_hn2 + sb.w);
        atomicAdd(&g_agg2[da.x], ha);
        atomicAdd(&g_agg2[da.y], hb);
        atomicAdd(&g_agg2[da.z], hc);
        atomicAdd(&g_agg2[da.w], hd);
        atomicAdd(&g_agg2[db.x], he);
        atomicAdd(&g_agg2[db.y], hf);
        atomicAdd(&g_agg2[db.z], hg);
        atomicAdd(&g_agg2[db.w], hh);
    } else if (t == E8) {
        for (int e = E8 * 8; e < E; e++)
            atomicAdd(&g_agg2[dst[e]], g_hn2[src[e]]);
    }
    PDL_TRIGGER();
}

// K6: final output + g_deg reset for next replay.
__global__ void k_final(float* __restrict__ out, const float* __restrict__ b2) {
    int n = blockIdx.x * blockDim.x + threadIdx.x;
    float bias = __ldg(b2);
    PDL_WAIT();
    if (n < N_NODES) {
        float d = g_deg[n];
        out[n] = fmaf(rsqrtf(d + 1.0f), __ldcv(&g_agg2[n]), bias);
        g_deg[n] = 0.0f;
    }
}

// ---------------------------------------------------------------------------
static void launch_pdl(void* fn, dim3 grid, dim3 block, size_t shmem,
                       void** args) {
    cudaLaunchConfig_t cfg = {};
    cfg.gridDim = grid;
    cfg.blockDim = block;
    cfg.dynamicSmemBytes = shmem;
    cfg.stream = (cudaStream_t)0;        // legacy default stream (captured)
    cudaLaunchAttribute attr[1];
    attr[0].id = cudaLaunchAttributeProgrammaticStreamSerialization;
    attr[0].val.programmaticStreamSerializationAllowed = 1;
    cfg.attrs = attr;
    cfg.numAttrs = 1;
    cudaLaunchKernelExC(&cfg, fn, args);
}

extern "C" void kernel_launch(void* const* d_in, const int* in_sizes, int n_in,
                              void* d_out, int out_size) {
    const float* x  = (const float*)d_in[0];
    const int*   ei = (const int*)d_in[1];
    const float* W1 = (const float*)d_in[2];
    const float* b1 = (const float*)d_in[3];
    const float* W2 = (const float*)d_in[4];
    const float* b2 = (const float*)d_in[5];
    float* out = (float*)d_out;

    int E = in_sizes[1] / 2;
    const int* src = ei;
    const int* dst = ei + E;

    int nb_nodes = (N_NODES + 255) / 256;
    int nb_gemm  = (N_NODES + NPB - 1) / NPB;
    int nb_deg   = ((E >> 2) + 1 + 255) / 256;
    int nb_e2    = ((E >> 3) + 1 + 255) / 256;
    int nb_scale = (N_NODES * 4 + 255) / 256;

    cudaFuncSetAttribute(k_fused, cudaFuncAttributeMaxDynamicSharedMemorySize,
                         GEMM_SMEM);

    {   // k_fused (PDL-dependent on previous replay's k_final via g_deg)
        int nbF = nb_gemm + nb_deg;
        void* a[] = {(void*)&x, (void*)&W1, (void*)&dst, (void*)&E, (void*)&nb_gemm};
        launch_pdl((void*)k_fused, dim3(nbF), dim3(256), GEMM_SMEM, a);
    }
    {
        void* a[] = {};
        launch_pdl((void*)k_scale, dim3(nb_scale), dim3(256), 0, a);
    }
    if ((E & 3) == 0) {
        int Eq = E >> 2;
        int nb_e1 = ((Eq * 4) + 255) / 256;
        void* a[] = {(void*)&src, (void*)&dst, (void*)&Eq};
        launch_pdl((void*)k_edge1_v4, dim3(nb_e1), dim3(256), 0, a);
    } else {
        int nb_e1 = ((E * 4) + 255) / 256;
        void* a[] = {(void*)&src, (void*)&dst, (void*)&E};
        launch_pdl((void*)k_edge1_s, dim3(nb_e1), dim3(256), 0, a);
    }
    {
        void* a[] = {(void*)&b1, (void*)&W2};
        launch_pdl((void*)k_node2, dim3(nb_nodes), dim3(256), 0, a);
    }
    {
        void* a[] = {(void*)&src, (void*)&dst, (void*)&E};
        launch_pdl((void*)k_edge2, dim3(nb_e2), dim3(256), 0, a);
    }
    {
        void* a[] = {(void*)&out, (void*)&b2};
        launch_pdl((void*)k_final, dim3(nb_nodes), dim3(256), 0, a);
    }
}